// round 5
// baseline (speedup 1.0000x reference)
#include <cuda_runtime.h>
#include <cuda_bf16.h>
#include <float.h>

#define W 128
#define BINS 50
#define NBOUND (BINS - 1)
#define MPAD 64              // padded row stride for mtm
#define THREADS 256
#define NWARP (THREADS / 32)

__global__ __launch_bounds__(THREADS, 8)
void mtf_kernel(const float* __restrict__ X, float* __restrict__ out, int S) {
    __shared__ float bnd[NBOUND];
    __shared__ __align__(16) int bins[W];
    __shared__ float mtm[BINS * MPAD];     // padded rows: bank(c) = c mod 32
    __shared__ float smn[NWARP], smx[NWARP];
    __shared__ float bmn, bmx;

    const int s    = blockIdx.x;
    const int tid  = threadIdx.x;
    const int lane = tid & 31;
    const int wid  = tid >> 5;

    if (s >= S) return;

    const float* x = X + (size_t)s * W;

    // Boundaries: linspace(-1, 1, 51)[1:-1].
    if (tid < NBOUND) {
        bnd[tid] = (float)(-1.0 + (2.0 * (double)(tid + 1)) / 50.0);
    }
    // Zero transition counts.
    for (int i = tid; i < BINS * MPAD; i += THREADS) mtm[i] = 0.0f;

    // Load series value (threads 0..127) and block min/max.
    float v = 0.0f;
    if (tid < W) v = x[tid];
    float mn = (tid < W) ? v : FLT_MAX;
    float mx = (tid < W) ? v : -FLT_MAX;
    #pragma unroll
    for (int o = 16; o > 0; o >>= 1) {
        mn = fminf(mn, __shfl_xor_sync(0xFFFFFFFFu, mn, o));
        mx = fmaxf(mx, __shfl_xor_sync(0xFFFFFFFFu, mx, o));
    }
    if (lane == 0) { smn[wid] = mn; smx[wid] = mx; }
    __syncthreads();                                   // S1
    if (wid == 0) {
        float a = (lane < NWARP) ? smn[lane] : FLT_MAX;
        float b = (lane < NWARP) ? smx[lane] : -FLT_MAX;
        #pragma unroll
        for (int o = 4; o > 0; o >>= 1) {
            a = fminf(a, __shfl_xor_sync(0xFFFFFFFFu, a, o));
            b = fmaxf(b, __shfl_xor_sync(0xFFFFFFFFu, b, o));
        }
        if (lane == 0) { bmn = a; bmx = b; }
    }
    __syncthreads();                                   // S2

    // Scale into [-1,1] (same op order as reference) and bucketize.
    if (tid < W) {
        float denom = bmx - bmn + 1e-6f;
        float t = (v - bmn) / denom;
        float xsc = t * 2.0f + (-1.0f);
        int cnt = 0;
        #pragma unroll
        for (int k = 0; k < NBOUND; k++) cnt += (bnd[k] < xsc) ? 1 : 0;
        bins[tid] = cnt;
    }
    __syncthreads();                                   // S3

    // Transition histogram (padded rows).
    if (tid < W - 1) {
        atomicAdd(&mtm[bins[tid] * MPAD + bins[tid + 1]], 1.0f);
    }
    // Each lane owns 4 CONTIGUOUS columns t2 = 4*lane .. 4*lane+3:
    // one conflict-free LDS.128 for the indices.
    const int4 c = reinterpret_cast<const int4*>(bins)[lane];
    __syncthreads();                                   // S4

    // For each bin-row this warp owns: lane-parallel row-sum, gather+scale
    // into a float4, ballot-match destination rows, coalesced STG.128.
    float* o = out + (size_t)s * W * W;
    for (int b1 = wid; b1 < BINS; b1 += NWARP) {
        const float* row = &mtm[b1 * MPAD];

        // row sum over 50 entries
        float part = row[lane] + ((lane < BINS - 32) ? row[lane + 32] : 0.0f);
        #pragma unroll
        for (int off = 16; off > 0; off >>= 1)
            part += __shfl_xor_sync(0xFFFFFFFFu, part, off);
        float rinv = (part == 0.0f) ? 1.0f : (1.0f / part);

        float4 val;
        val.x = row[c.x] * rinv;
        val.y = row[c.y] * rinv;
        val.z = row[c.z] * rinv;
        val.w = row[c.w] * rinv;

        // all t1 with bins[t1] == b1 get this row; t1 = 4*idx + j
        unsigned m0 = __ballot_sync(0xFFFFFFFFu, c.x == b1);
        unsigned m1 = __ballot_sync(0xFFFFFFFFu, c.y == b1);
        unsigned m2 = __ballot_sync(0xFFFFFFFFu, c.z == b1);
        unsigned m3 = __ballot_sync(0xFFFFFFFFu, c.w == b1);
        while (m0) {
            int t1 = 4 * (__ffs(m0) - 1); m0 &= m0 - 1;
            reinterpret_cast<float4*>(o + t1 * W)[lane] = val;
        }
        while (m1) {
            int t1 = 4 * (__ffs(m1) - 1) + 1; m1 &= m1 - 1;
            reinterpret_cast<float4*>(o + t1 * W)[lane] = val;
        }
        while (m2) {
            int t1 = 4 * (__ffs(m2) - 1) + 2; m2 &= m2 - 1;
            reinterpret_cast<float4*>(o + t1 * W)[lane] = val;
        }
        while (m3) {
            int t1 = 4 * (__ffs(m3) - 1) + 3; m3 &= m3 - 1;
            reinterpret_cast<float4*>(o + t1 * W)[lane] = val;
        }
    }
}

extern "C" void kernel_launch(void* const* d_in, const int* in_sizes, int n_in,
                              void* d_out, int out_size) {
    const float* X = (const float*)d_in[0];
    float* out = (float*)d_out;
    int S = in_sizes[0] / W;   // 256*6 = 1536 series
    mtf_kernel<<<S, THREADS>>>(X, out, S);
}